// round 1
// baseline (speedup 1.0000x reference)
#include <cuda_runtime.h>
#include <math.h>

#define S     2048
#define HQ    16
#define HKV   8
#define DH    128
#define HIDN  2048
#define QKVN  4096
#define SCALE 0.08838834764831845f

// -------- scratch (no allocations allowed) --------
__device__ float g_qkv[(size_t)S * QKVN];      // 32 MB  [s][4096]
__device__ float g_q[(size_t)HQ * S * DH];     // 16 MB  [h][s][d]
__device__ float g_k[(size_t)HKV * S * DH];    //  8 MB  [kvh][s][d]
__device__ float g_attn[(size_t)S * HQ * DH];  // 16 MB  [s][h*128+d]

// ============================================================
// C[m][n] = sum_k A[m][k] * B[n][k] + bias[n]
// 128x128 block tile, BK=8, 256 threads, 8x8 per thread.
// M,N multiples of 128; K multiple of 8.
// ============================================================
__global__ __launch_bounds__(256, 2)
void sgemm_abt(const float* __restrict__ A, const float* __restrict__ B,
               const float* __restrict__ bias, float* __restrict__ C,
               int M, int N, int K)
{
    __shared__ float As[8][128];
    __shared__ float Bs[8][128];
    const int tid = threadIdx.x;
    const int bm = blockIdx.y * 128;
    const int bn = blockIdx.x * 128;
    const int tx = tid & 15;
    const int ty = tid >> 4;
    const int lm = tid >> 1;           // 0..127
    const int lk = (tid & 1) * 4;      // 0 or 4

    float acc[8][8];
    #pragma unroll
    for (int i = 0; i < 8; i++)
        #pragma unroll
        for (int j = 0; j < 8; j++) acc[i][j] = 0.f;

    const float* Ap = A + (size_t)(bm + lm) * K + lk;
    const float* Bp = B + (size_t)(bn + lm) * K + lk;

    for (int k0 = 0; k0 < K; k0 += 8) {
        float4 a4 = *(const float4*)(Ap + k0);
        float4 b4 = *(const float4*)(Bp + k0);
        As[lk+0][lm] = a4.x; As[lk+1][lm] = a4.y;
        As[lk+2][lm] = a4.z; As[lk+3][lm] = a4.w;
        Bs[lk+0][lm] = b4.x; Bs[lk+1][lm] = b4.y;
        Bs[lk+2][lm] = b4.z; Bs[lk+3][lm] = b4.w;
        __syncthreads();
        #pragma unroll
        for (int kk = 0; kk < 8; kk++) {
            float ra[8], rb[8];
            *(float4*)(ra)     = *(const float4*)&As[kk][ty*4];
            *(float4*)(ra + 4) = *(const float4*)&As[kk][ty*4 + 64];
            *(float4*)(rb)     = *(const float4*)&Bs[kk][tx*4];
            *(float4*)(rb + 4) = *(const float4*)&Bs[kk][tx*4 + 64];
            #pragma unroll
            for (int i = 0; i < 8; i++)
                #pragma unroll
                for (int j = 0; j < 8; j++)
                    acc[i][j] += ra[i] * rb[j];
        }
        __syncthreads();
    }

    float4 bb0 = *(const float4*)(bias + bn + tx*4);
    float4 bb1 = *(const float4*)(bias + bn + tx*4 + 64);
    #pragma unroll
    for (int i = 0; i < 8; i++) {
        int mm = bm + ty*4 + (i < 4 ? i : 60 + i);
        float4 o0, o1;
        o0.x = acc[i][0] + bb0.x; o0.y = acc[i][1] + bb0.y;
        o0.z = acc[i][2] + bb0.z; o0.w = acc[i][3] + bb0.w;
        o1.x = acc[i][4] + bb1.x; o1.y = acc[i][5] + bb1.y;
        o1.z = acc[i][6] + bb1.z; o1.w = acc[i][7] + bb1.w;
        *(float4*)(C + (size_t)mm * N + bn + tx*4)      = o0;
        *(float4*)(C + (size_t)mm * N + bn + tx*4 + 64) = o1;
    }
}

// ============================================================
// RMSNorm (per 64-dim half) + triple RoPE.
// grid (S, 24): blockIdx.y 0..15 -> q head, 16..23 -> k head.
// 128 threads = one dim each.
// ============================================================
__global__ __launch_bounds__(128)
void normrope_kernel(const float* __restrict__ qkv, const int* __restrict__ indexes,
                     const float* __restrict__ qnw, const float* __restrict__ knw,
                     const float* __restrict__ qnhw, const float* __restrict__ knhw,
                     float* __restrict__ Qo, float* __restrict__ Ko)
{
    const int s = blockIdx.x;
    const int h = blockIdx.y;
    const int d = threadIdx.x;
    const bool isq = (h < HQ);

    const float* row = qkv + (size_t)s * QKVN + (isq ? h*DH : HQ*DH + (h - HQ)*DH);
    float x = row[d];

    // sum of squares per 64-dim half (warps 0,1 = half0; 2,3 = half1)
    float v = x * x;
    #pragma unroll
    for (int o = 16; o > 0; o >>= 1) v += __shfl_xor_sync(0xffffffffu, v, o);
    __shared__ float ws[4];
    if ((d & 31) == 0) ws[d >> 5] = v;
    __syncthreads();
    const int half = d >> 6;
    float var = (ws[half*2] + ws[half*2 + 1]) * (1.f / 64.f);
    const float* w = isq ? (half ? qnhw : qnw) : (half ? knhw : knw);
    float xn = w[d & 63] * x * rsqrtf(var + 1e-6f);

    __shared__ float xs[128];
    xs[d] = xn;
    __syncthreads();

    float outv;
    if (d < 64) {
        // time RoPE: 64-dim, 32 freqs, theta=1e6
        int i = d, jj = d & 31;
        float pos = (float)indexes[s];
        float f = powf(1000000.0f, -(float)jj * (1.0f / 32.0f));
        float a = pos * f;
        float c = cosf(a), sn = sinf(a);
        float prt = (i < 32) ? xs[d + 32] : xs[d - 32];
        outv = (i < 32) ? xn * c - prt * sn : xn * c + prt * sn;
    } else {
        // h / w RoPE: 32-dim each, 16 freqs, theta=1e4
        int seg = (d < 96) ? 1 : 2;
        int base = (d < 96) ? 64 : 96;
        int i = d - base;              // 0..31
        int jj = i & 15;
        float pos = (float)indexes[seg * S + s];
        float f = powf(10000.0f, -(float)jj * (1.0f / 16.0f));
        float a = pos * f;
        float c = cosf(a), sn = sinf(a);
        float prt = (i < 16) ? xs[base + i + 16] : xs[base + i - 16];
        outv = (i < 16) ? xn * c - prt * sn : xn * c + prt * sn;
    }

    if (isq) Qo[((size_t)h * S + s) * DH + d] = outv;
    else     Ko[((size_t)(h - HQ) * S + s) * DH + d] = outv;
}

// ============================================================
// Causal flash attention, fp32.
// grid (S/16, HQ); 128 threads = 16 query-groups x 8 lanes.
// Lane j owns dims {32i + 4j + c}: LDS.128 conflict-free.
// V read in place from g_qkv (stride 4096).
// ============================================================
__global__ __launch_bounds__(128)
void attn_kernel(const float* __restrict__ Q, const float* __restrict__ Kh,
                 const float* __restrict__ qkv, float* __restrict__ Out)
{
    const int qb = blockIdx.x;
    const int h = blockIdx.y;
    const int kvh = h >> 1;             // n_rep = 2
    const int tid = threadIdx.x;
    const int g = tid >> 3;
    const int j = tid & 7;
    const int sq = qb * 16 + g;

    __shared__ float Ks[16][128];
    __shared__ float Vs[16][128];

    const float* qrow = Q + ((size_t)h * S + sq) * DH;
    float qreg[16];
    #pragma unroll
    for (int i = 0; i < 4; i++) {
        float4 qv = *(const float4*)(qrow + i*32 + 4*j);
        qreg[4*i+0] = qv.x; qreg[4*i+1] = qv.y;
        qreg[4*i+2] = qv.z; qreg[4*i+3] = qv.w;
    }

    float o[16];
    #pragma unroll
    for (int i = 0; i < 16; i++) o[i] = 0.f;
    float m = -1e30f, l = 0.f;

    const float* Kbase = Kh + (size_t)kvh * S * DH;
    const float* Vbase = qkv + HQ*DH + HKV*DH + kvh*DH;   // v block offset 3072

    const int kend = qb * 16 + 16;
    for (int kt0 = 0; kt0 < kend; kt0 += 16) {
        #pragma unroll
        for (int u = 0; u < 4; u++) {
            int idx4 = u * 128 + tid;
            int r = idx4 >> 5;
            int c = (idx4 & 31) * 4;
            *(float4*)&Ks[r][c] = *(const float4*)(Kbase + (size_t)(kt0 + r) * DH + c);
            *(float4*)&Vs[r][c] = *(const float4*)(Vbase + (size_t)(kt0 + r) * QKVN + c);
        }
        __syncthreads();

        float sc[16];
        #pragma unroll
        for (int t = 0; t < 16; t++) {
            float s0 = 0.f;
            #pragma unroll
            for (int i = 0; i < 4; i++) {
                float4 kv = *(const float4*)&Ks[t][i*32 + 4*j];
                s0 += qreg[4*i+0]*kv.x + qreg[4*i+1]*kv.y
                    + qreg[4*i+2]*kv.z + qreg[4*i+3]*kv.w;
            }
            s0 += __shfl_xor_sync(0xffffffffu, s0, 1);
            s0 += __shfl_xor_sync(0xffffffffu, s0, 2);
            s0 += __shfl_xor_sync(0xffffffffu, s0, 4);
            sc[t] = (kt0 + t <= sq) ? s0 * SCALE : -1e30f;
        }

        float tm = m;
        #pragma unroll
        for (int t = 0; t < 16; t++) tm = fmaxf(tm, sc[t]);
        float alpha = __expf(m - tm);
        l *= alpha;
        #pragma unroll
        for (int i = 0; i < 16; i++) o[i] *= alpha;
        #pragma unroll
        for (int t = 0; t < 16; t++) {
            float p = __expf(sc[t] - tm);
            l += p;
            #pragma unroll
            for (int i = 0; i < 4; i++) {
                float4 vv = *(const float4*)&Vs[t][i*32 + 4*j];
                o[4*i+0] += p * vv.x; o[4*i+1] += p * vv.y;
                o[4*i+2] += p * vv.z; o[4*i+3] += p * vv.w;
            }
        }
        m = tm;
        __syncthreads();
    }

    float inv = 1.f / l;
    float* orow = Out + (size_t)sq * (HQ * DH) + h * DH;
    #pragma unroll
    for (int i = 0; i < 4; i++) {
        float4 ov;
        ov.x = o[4*i+0]*inv; ov.y = o[4*i+1]*inv;
        ov.z = o[4*i+2]*inv; ov.w = o[4*i+3]*inv;
        *(float4*)(orow + i*32 + 4*j) = ov;
    }
}

// ============================================================
extern "C" void kernel_launch(void* const* d_in, const int* in_sizes, int n_in,
                              void* d_out, int out_size)
{
    const float* hidden  = (const float*)d_in[0];
    const int*   indexes = (const int*)  d_in[1];
    // d_in[2] = attention_mask (causal by construction; applied analytically)
    const float* qkv_w   = (const float*)d_in[3];
    const float* qkv_b   = (const float*)d_in[4];
    const float* o_w     = (const float*)d_in[5];
    const float* o_b     = (const float*)d_in[6];
    const float* qnw     = (const float*)d_in[7];
    const float* knw     = (const float*)d_in[8];
    const float* qnhw    = (const float*)d_in[9];
    const float* knhw    = (const float*)d_in[10];
    float* out = (float*)d_out;

    float *p_qkv, *p_q, *p_k, *p_attn;
    cudaGetSymbolAddress((void**)&p_qkv,  g_qkv);
    cudaGetSymbolAddress((void**)&p_q,    g_q);
    cudaGetSymbolAddress((void**)&p_k,    g_k);
    cudaGetSymbolAddress((void**)&p_attn, g_attn);

    // 1) QKV projection
    sgemm_abt<<<dim3(QKVN/128, S/128), 256>>>(hidden, qkv_w, qkv_b, p_qkv, S, QKVN, HIDN);
    // 2) RMSNorm halves + triple RoPE -> Q [H,S,D], K [KV,S,D]
    normrope_kernel<<<dim3(S, HQ + HKV), 128>>>(p_qkv, indexes, qnw, knw, qnhw, knhw, p_q, p_k);
    // 3) Causal GQA flash attention -> attn [S, H*D]
    attn_kernel<<<dim3(S/16, HQ), 128>>>(p_q, p_k, p_qkv, p_attn);
    // 4) Output projection
    sgemm_abt<<<dim3(HIDN/128, S/128), 256>>>(p_attn, o_w, o_b, out, S, HIDN, HIDN);
}

// round 3
// speedup vs baseline: 1.4852x; 1.4852x over previous
#include <cuda_runtime.h>
#include <math.h>

#define S     2048
#define HQ    16
#define HKV   8
#define DH    128
#define HIDN  2048
#define QKVN  4096
#define SCALE 0.08838834764831845f

#define BQ 64
#define BK 64

// -------- scratch (no allocations allowed) --------
__device__ float g_qkv[(size_t)S * QKVN];      // 32 MB  [s][4096]
__device__ float g_q[(size_t)HQ * DH * S];     // 16 MB  [h][d][s]  (transposed)
__device__ float g_k[(size_t)HKV * DH * S];    //  8 MB  [kvh][d][s] (transposed)
__device__ float g_attn[(size_t)S * HQ * DH];  // 16 MB  [s][h*128+d]

// ============================================================
// C[m][n] = sum_k A[m][k] * B[n][k] + bias[n]
// 128x128 block tile, BK=8, 256 threads, 8x8 per thread.
// Next k-slab global loads prefetched into registers.
// ============================================================
__global__ __launch_bounds__(256, 2)
void sgemm_abt(const float* __restrict__ A, const float* __restrict__ B,
               const float* __restrict__ bias, float* __restrict__ C,
               int M, int N, int K)
{
    __shared__ float As[8][128];
    __shared__ float Bs[8][128];
    const int tid = threadIdx.x;
    const int bm = blockIdx.y * 128;
    const int bn = blockIdx.x * 128;
    const int tx = tid & 15;
    const int ty = tid >> 4;
    const int lm = tid >> 1;           // 0..127
    const int lk = (tid & 1) * 4;      // 0 or 4

    float acc[8][8];
    #pragma unroll
    for (int i = 0; i < 8; i++)
        #pragma unroll
        for (int j = 0; j < 8; j++) acc[i][j] = 0.f;

    const float* Ap = A + (size_t)(bm + lm) * K + lk;
    const float* Bp = B + (size_t)(bn + lm) * K + lk;

    float4 a4 = *(const float4*)(Ap);
    float4 b4 = *(const float4*)(Bp);

    for (int k0 = 0; k0 < K; k0 += 8) {
        As[lk+0][lm] = a4.x; As[lk+1][lm] = a4.y;
        As[lk+2][lm] = a4.z; As[lk+3][lm] = a4.w;
        Bs[lk+0][lm] = b4.x; Bs[lk+1][lm] = b4.y;
        Bs[lk+2][lm] = b4.z; Bs[lk+3][lm] = b4.w;
        __syncthreads();
        if (k0 + 8 < K) {
            a4 = *(const float4*)(Ap + k0 + 8);
            b4 = *(const float4*)(Bp + k0 + 8);
        }
        #pragma unroll
        for (int kk = 0; kk < 8; kk++) {
            float ra[8], rb[8];
            *(float4*)(ra)     = *(const float4*)&As[kk][ty*4];
            *(float4*)(ra + 4) = *(const float4*)&As[kk][ty*4 + 64];
            *(float4*)(rb)     = *(const float4*)&Bs[kk][tx*4];
            *(float4*)(rb + 4) = *(const float4*)&Bs[kk][tx*4 + 64];
            #pragma unroll
            for (int i = 0; i < 8; i++)
                #pragma unroll
                for (int j = 0; j < 8; j++)
                    acc[i][j] += ra[i] * rb[j];
        }
        __syncthreads();
    }

    float4 bb0 = *(const float4*)(bias + bn + tx*4);
    float4 bb1 = *(const float4*)(bias + bn + tx*4 + 64);
    #pragma unroll
    for (int i = 0; i < 8; i++) {
        int mm = bm + ty*4 + (i < 4 ? i : 60 + i);
        float4 o0, o1;
        o0.x = acc[i][0] + bb0.x; o0.y = acc[i][1] + bb0.y;
        o0.z = acc[i][2] + bb0.z; o0.w = acc[i][3] + bb0.w;
        o1.x = acc[i][4] + bb1.x; o1.y = acc[i][5] + bb1.y;
        o1.z = acc[i][6] + bb1.z; o1.w = acc[i][7] + bb1.w;
        *(float4*)(C + (size_t)mm * N + bn + tx*4)      = o0;
        *(float4*)(C + (size_t)mm * N + bn + tx*4 + 64) = o1;
    }
}

// ============================================================
// RMSNorm (per 64-dim half) + triple RoPE.
// Writes Q/K TRANSPOSED to global: [h][d][s].
// ============================================================
__global__ __launch_bounds__(128)
void normrope_kernel(const float* __restrict__ qkv, const int* __restrict__ indexes,
                     const float* __restrict__ qnw, const float* __restrict__ knw,
                     const float* __restrict__ qnhw, const float* __restrict__ knhw,
                     float* __restrict__ Qo, float* __restrict__ Ko)
{
    const int s = blockIdx.x;
    const int h = blockIdx.y;
    const int d = threadIdx.x;
    const bool isq = (h < HQ);

    const float* row = qkv + (size_t)s * QKVN + (isq ? h*DH : HQ*DH + (h - HQ)*DH);
    float x = row[d];

    float v = x * x;
    #pragma unroll
    for (int o = 16; o > 0; o >>= 1) v += __shfl_xor_sync(0xffffffffu, v, o);
    __shared__ float ws[4];
    if ((d & 31) == 0) ws[d >> 5] = v;
    __syncthreads();
    const int half = d >> 6;
    float var = (ws[half*2] + ws[half*2 + 1]) * (1.f / 64.f);
    const float* w = isq ? (half ? qnhw : qnw) : (half ? knhw : knw);
    float xn = w[d & 63] * x * rsqrtf(var + 1e-6f);

    __shared__ float xs[128];
    xs[d] = xn;
    __syncthreads();

    float outv;
    if (d < 64) {
        int i = d, jj = d & 31;
        float pos = (float)indexes[s];
        float f = powf(1000000.0f, -(float)jj * (1.0f / 32.0f));
        float a = pos * f;
        float c = cosf(a), sn = sinf(a);
        float prt = (i < 32) ? xs[d + 32] : xs[d - 32];
        outv = (i < 32) ? xn * c - prt * sn : xn * c + prt * sn;
    } else {
        int seg = (d < 96) ? 1 : 2;
        int base = (d < 96) ? 64 : 96;
        int i = d - base;
        int jj = i & 15;
        float pos = (float)indexes[seg * S + s];
        float f = powf(10000.0f, -(float)jj * (1.0f / 16.0f));
        float a = pos * f;
        float c = cosf(a), sn = sinf(a);
        float prt = (i < 16) ? xs[base + i + 16] : xs[base + i - 16];
        outv = (i < 16) ? xn * c - prt * sn : xn * c + prt * sn;
    }

    if (isq) Qo[((size_t)h * DH + d) * S + s] = outv;
    else     Ko[((size_t)(h - HQ) * DH + d) * S + s] = outv;
}

// ============================================================
// Causal flash attention v3: register-blocked GEMM-GEMM.
// Q/K arrive transposed [h][d][s] -> straight float4 copies into
// Qs/Ks [d][q] at even stride 68 (16B aligned, conflict-free).
// Score: (tx,ty) 16x16 -> 4q x 4k per thread, LDS.128 operands.
// P staged [k][q] at stride 65, scalar access only.
// PV: (vx,vy) 32x8 -> 8q x 4d per thread.
// ============================================================
#define SQK 68
#define SP  65
#define QS_OFF 0
#define KS_OFF (128*SQK)
#define VS_OFF (KS_OFF + 128*SQK)
#define PS_OFF (VS_OFF + 64*128)
#define AL_OFF (PS_OFF + 64*SP)
#define LS_OFF (AL_OFF + 64)
#define ATTN_SMEM_FLOATS (LS_OFF + 64)
#define ATTN_SMEM_BYTES (ATTN_SMEM_FLOATS * 4)

__global__ __launch_bounds__(256, 1)
void attn3_kernel(const float* __restrict__ Q, const float* __restrict__ Kh,
                  const float* __restrict__ qkv, float* __restrict__ Out)
{
    extern __shared__ float sm[];
    float* Qs = sm + QS_OFF;
    float* Ks = sm + KS_OFF;
    float* Vs = sm + VS_OFF;
    float* Ps = sm + PS_OFF;
    float* als = sm + AL_OFF;
    float* ls  = sm + LS_OFF;

    const int qb = (int)(gridDim.x - 1 - blockIdx.x);   // longest first
    const int h  = blockIdx.y;
    const int kvh = h >> 1;
    const int q0 = qb * BQ;
    const int tid = threadIdx.x;
    const int tx = tid & 15, ty = tid >> 4;   // score mapping
    const int vx = tid & 31, vy = tid >> 5;   // PV mapping

    // ---- load Q tile: Qs[d][q] straight from transposed global ----
    const float* Qbase = Q + (size_t)h * DH * S + q0;
    #pragma unroll
    for (int u = 0; u < 8; u++) {
        int idx = u * 256 + tid;
        int dd = idx >> 4;             // 0..127
        int qq = (idx & 15) * 4;       // 0..60
        float4 q4 = *(const float4*)(Qbase + (size_t)dd * S + qq);
        *(float4*)&Qs[dd*SQK + qq] = q4;
    }

    float o[8][4];
    #pragma unroll
    for (int i = 0; i < 8; i++)
        #pragma unroll
        for (int c = 0; c < 4; c++) o[i][c] = 0.f;
    float m[4], l[4];
    #pragma unroll
    for (int i = 0; i < 4; i++) { m[i] = -1e30f; l[i] = 0.f; }

    const float* Kbase = Kh + (size_t)kvh * DH * S;
    const float* Vbase = qkv + HQ*DH + HKV*DH + kvh*DH;   // V in qkv, stride QKVN

    for (int kt0 = 0; kt0 < q0 + BQ; kt0 += BK) {
        __syncthreads();   // previous PV done reading Ks/Vs/Ps

        // ---- K tile transposed-copy Ks[d][k]; V tile natural Vs[k][d] ----
        #pragma unroll
        for (int u = 0; u < 8; u++) {
            int idx = u * 256 + tid;
            int dd = idx >> 4;
            int kk = (idx & 15) * 4;
            float4 k4 = *(const float4*)(Kbase + (size_t)dd * S + kt0 + kk);
            *(float4*)&Ks[dd*SQK + kk] = k4;
            int r = idx >> 5;
            int c = (idx & 31) * 4;
            float4 v4 = *(const float4*)(Vbase + (size_t)(kt0 + r) * QKVN + c);
            *(float4*)&Vs[r*128 + c] = v4;
        }
        __syncthreads();

        // ---- score GEMM: sc[4q][4k] ----
        float sc[4][4];
        #pragma unroll
        for (int i = 0; i < 4; i++)
            #pragma unroll
            for (int j = 0; j < 4; j++) sc[i][j] = 0.f;

        #pragma unroll 8
        for (int dd = 0; dd < 128; dd++) {
            float4 ra = *(const float4*)&Qs[dd*SQK + ty*4];
            float4 rb = *(const float4*)&Ks[dd*SQK + tx*4];
            float a[4] = {ra.x, ra.y, ra.z, ra.w};
            float b[4] = {rb.x, rb.y, rb.z, rb.w};
            #pragma unroll
            for (int i = 0; i < 4; i++)
                #pragma unroll
                for (int j = 0; j < 4; j++)
                    sc[i][j] += a[i] * b[j];
        }

        // ---- mask + scale (diagonal tile only) ----
        const bool needMask = (kt0 + BK - 1 > q0);
        #pragma unroll
        for (int i = 0; i < 4; i++) {
            int sq = q0 + ty*4 + i;
            #pragma unroll
            for (int j = 0; j < 4; j++) {
                int sk = kt0 + tx*4 + j;
                float v = sc[i][j] * SCALE;
                sc[i][j] = (!needMask || sk <= sq) ? v : -1e30f;
            }
        }

        // ---- online softmax (row groups = 16 lanes via shfl) ----
        float alpha[4];
        #pragma unroll
        for (int i = 0; i < 4; i++) {
            float rm = fmaxf(fmaxf(sc[i][0], sc[i][1]), fmaxf(sc[i][2], sc[i][3]));
            rm = fmaxf(rm, __shfl_xor_sync(0xffffffffu, rm, 1));
            rm = fmaxf(rm, __shfl_xor_sync(0xffffffffu, rm, 2));
            rm = fmaxf(rm, __shfl_xor_sync(0xffffffffu, rm, 4));
            rm = fmaxf(rm, __shfl_xor_sync(0xffffffffu, rm, 8));
            float mn = fmaxf(m[i], rm);
            alpha[i] = __expf(m[i] - mn);
            m[i] = mn;
            float rs = 0.f;
            #pragma unroll
            for (int j = 0; j < 4; j++) {
                float p = __expf(sc[i][j] - mn);
                sc[i][j] = p;
                rs += p;
            }
            rs += __shfl_xor_sync(0xffffffffu, rs, 1);
            rs += __shfl_xor_sync(0xffffffffu, rs, 2);
            rs += __shfl_xor_sync(0xffffffffu, rs, 4);
            rs += __shfl_xor_sync(0xffffffffu, rs, 8);
            l[i] = l[i] * alpha[i] + rs;
        }

        // ---- stage P[k][q] (scalar, stride 65 => 2-way max) + alpha ----
        #pragma unroll
        for (int j = 0; j < 4; j++)
            #pragma unroll
            for (int i = 0; i < 4; i++)
                Ps[(tx*4 + j)*SP + ty*4 + i] = sc[i][j];
        if (tx == 0) {
            #pragma unroll
            for (int i = 0; i < 4; i++) als[ty*4 + i] = alpha[i];
        }
        __syncthreads();

        // ---- PV: rescale + accumulate ----
        #pragma unroll
        for (int i = 0; i < 8; i++) {
            float a = als[vy*8 + i];
            #pragma unroll
            for (int c = 0; c < 4; c++) o[i][c] *= a;
        }
        #pragma unroll 4
        for (int kk = 0; kk < BK; kk++) {
            float ra[8];
            #pragma unroll
            for (int i = 0; i < 8; i++) ra[i] = Ps[kk*SP + vy*8 + i];  // broadcast
            float4 rb = *(const float4*)&Vs[kk*128 + vx*4];
            #pragma unroll
            for (int i = 0; i < 8; i++) {
                o[i][0] += ra[i] * rb.x;
                o[i][1] += ra[i] * rb.y;
                o[i][2] += ra[i] * rb.z;
                o[i][3] += ra[i] * rb.w;
            }
        }
    }

    // ---- epilogue ----
    if (tx == 0) {
        #pragma unroll
        for (int i = 0; i < 4; i++) ls[ty*4 + i] = l[i];
    }
    __syncthreads();
    #pragma unroll
    for (int i = 0; i < 8; i++) {
        float inv = 1.f / ls[vy*8 + i];
        float4 ov;
        ov.x = o[i][0]*inv; ov.y = o[i][1]*inv;
        ov.z = o[i][2]*inv; ov.w = o[i][3]*inv;
        *(float4*)(Out + (size_t)(q0 + vy*8 + i) * (HQ*DH) + h*DH + vx*4) = ov;
    }
}

// ============================================================
extern "C" void kernel_launch(void* const* d_in, const int* in_sizes, int n_in,
                              void* d_out, int out_size)
{
    const float* hidden  = (const float*)d_in[0];
    const int*   indexes = (const int*)  d_in[1];
    // d_in[2] = attention_mask (causal by construction; applied analytically)
    const float* qkv_w   = (const float*)d_in[3];
    const float* qkv_b   = (const float*)d_in[4];
    const float* o_w     = (const float*)d_in[5];
    const float* o_b     = (const float*)d_in[6];
    const float* qnw     = (const float*)d_in[7];
    const float* knw     = (const float*)d_in[8];
    const float* qnhw    = (const float*)d_in[9];
    const float* knhw    = (const float*)d_in[10];
    float* out = (float*)d_out;

    float *p_qkv, *p_q, *p_k, *p_attn;
    cudaGetSymbolAddress((void**)&p_qkv,  g_qkv);
    cudaGetSymbolAddress((void**)&p_q,    g_q);
    cudaGetSymbolAddress((void**)&p_k,    g_k);
    cudaGetSymbolAddress((void**)&p_attn, g_attn);

    cudaFuncSetAttribute(attn3_kernel,
                         cudaFuncAttributeMaxDynamicSharedMemorySize, ATTN_SMEM_BYTES);

    // 1) QKV projection
    sgemm_abt<<<dim3(QKVN/128, S/128), 256>>>(hidden, qkv_w, qkv_b, p_qkv, S, QKVN, HIDN);
    // 2) RMSNorm halves + triple RoPE -> Q [H,D,S], K [KV,D,S] (transposed)
    normrope_kernel<<<dim3(S, HQ + HKV), 128>>>(p_qkv, indexes, qnw, knw, qnhw, knhw, p_q, p_k);
    // 3) Causal GQA flash attention -> attn [S, H*D]
    attn3_kernel<<<dim3(S/BQ, HQ), 256, ATTN_SMEM_BYTES>>>(p_q, p_k, p_qkv, p_attn);
    // 4) Output projection
    sgemm_abt<<<dim3(HIDN/128, S/128), 256>>>(p_attn, o_w, o_b, out, S, HIDN, HIDN);
}

// round 4
// speedup vs baseline: 1.5094x; 1.0163x over previous
#include <cuda_runtime.h>
#include <math.h>
#include <stdint.h>

#define S     2048
#define HQ    16
#define HKV   8
#define DH    128
#define HIDN  2048
#define QKVN  4096
#define SCALE 0.08838834764831845f

#define BQ 64
#define BK 64

// -------- scratch (no allocations allowed) --------
__device__ float g_qkv[(size_t)S * QKVN];      // 32 MB  [s][4096]
__device__ float g_q[(size_t)HQ * DH * S];     // 16 MB  [h][d][s]  (transposed)
__device__ float g_k[(size_t)HKV * DH * S];    //  8 MB  [kvh][d][s] (transposed)
__device__ float g_attn[(size_t)S * HQ * DH];  // 16 MB  [s][h*128+d]

// -------- cp.async helpers --------
__device__ __forceinline__ uint32_t smem_u32(const void* p) {
    return (uint32_t)__cvta_generic_to_shared(p);
}
__device__ __forceinline__ void cp_async16(uint32_t dst, const void* src) {
    asm volatile("cp.async.cg.shared.global [%0], [%1], 16;" :: "r"(dst), "l"(src));
}
__device__ __forceinline__ void cp_commit() {
    asm volatile("cp.async.commit_group;");
}
template<int N> __device__ __forceinline__ void cp_wait() {
    asm volatile("cp.async.wait_group %0;" :: "n"(N));
}

// ============================================================
// C[m][n] = sum_k A[m][k] * B[n][k] + bias[n]
// 128x128 block tile, BK=8, 256 threads, 8x8 per thread.
// ============================================================
__global__ __launch_bounds__(256, 2)
void sgemm_abt(const float* __restrict__ A, const float* __restrict__ B,
               const float* __restrict__ bias, float* __restrict__ C,
               int M, int N, int K)
{
    __shared__ float As[8][128];
    __shared__ float Bs[8][128];
    const int tid = threadIdx.x;
    const int bm = blockIdx.y * 128;
    const int bn = blockIdx.x * 128;
    const int tx = tid & 15;
    const int ty = tid >> 4;
    const int lm = tid >> 1;           // 0..127
    const int lk = (tid & 1) * 4;      // 0 or 4

    float acc[8][8];
    #pragma unroll
    for (int i = 0; i < 8; i++)
        #pragma unroll
        for (int j = 0; j < 8; j++) acc[i][j] = 0.f;

    const float* Ap = A + (size_t)(bm + lm) * K + lk;
    const float* Bp = B + (size_t)(bn + lm) * K + lk;

    float4 a4 = *(const float4*)(Ap);
    float4 b4 = *(const float4*)(Bp);

    for (int k0 = 0; k0 < K; k0 += 8) {
        As[lk+0][lm] = a4.x; As[lk+1][lm] = a4.y;
        As[lk+2][lm] = a4.z; As[lk+3][lm] = a4.w;
        Bs[lk+0][lm] = b4.x; Bs[lk+1][lm] = b4.y;
        Bs[lk+2][lm] = b4.z; Bs[lk+3][lm] = b4.w;
        __syncthreads();
        if (k0 + 8 < K) {
            a4 = *(const float4*)(Ap + k0 + 8);
            b4 = *(const float4*)(Bp + k0 + 8);
        }
        #pragma unroll
        for (int kk = 0; kk < 8; kk++) {
            float ra[8], rb[8];
            *(float4*)(ra)     = *(const float4*)&As[kk][ty*4];
            *(float4*)(ra + 4) = *(const float4*)&As[kk][ty*4 + 64];
            *(float4*)(rb)     = *(const float4*)&Bs[kk][tx*4];
            *(float4*)(rb + 4) = *(const float4*)&Bs[kk][tx*4 + 64];
            #pragma unroll
            for (int i = 0; i < 8; i++)
                #pragma unroll
                for (int j = 0; j < 8; j++)
                    acc[i][j] += ra[i] * rb[j];
        }
        __syncthreads();
    }

    float4 bb0 = *(const float4*)(bias + bn + tx*4);
    float4 bb1 = *(const float4*)(bias + bn + tx*4 + 64);
    #pragma unroll
    for (int i = 0; i < 8; i++) {
        int mm = bm + ty*4 + (i < 4 ? i : 60 + i);
        float4 o0, o1;
        o0.x = acc[i][0] + bb0.x; o0.y = acc[i][1] + bb0.y;
        o0.z = acc[i][2] + bb0.z; o0.w = acc[i][3] + bb0.w;
        o1.x = acc[i][4] + bb1.x; o1.y = acc[i][5] + bb1.y;
        o1.z = acc[i][6] + bb1.z; o1.w = acc[i][7] + bb1.w;
        *(float4*)(C + (size_t)mm * N + bn + tx*4)      = o0;
        *(float4*)(C + (size_t)mm * N + bn + tx*4 + 64) = o1;
    }
}

// ============================================================
// RMSNorm (per 64-dim half) + triple RoPE.
// Writes Q/K TRANSPOSED to global: [h][d][s].
// ============================================================
__global__ __launch_bounds__(128)
void normrope_kernel(const float* __restrict__ qkv, const int* __restrict__ indexes,
                     const float* __restrict__ qnw, const float* __restrict__ knw,
                     const float* __restrict__ qnhw, const float* __restrict__ knhw,
                     float* __restrict__ Qo, float* __restrict__ Ko)
{
    const int s = blockIdx.x;
    const int h = blockIdx.y;
    const int d = threadIdx.x;
    const bool isq = (h < HQ);

    const float* row = qkv + (size_t)s * QKVN + (isq ? h*DH : HQ*DH + (h - HQ)*DH);
    float x = row[d];

    float v = x * x;
    #pragma unroll
    for (int o = 16; o > 0; o >>= 1) v += __shfl_xor_sync(0xffffffffu, v, o);
    __shared__ float ws[4];
    if ((d & 31) == 0) ws[d >> 5] = v;
    __syncthreads();
    const int half = d >> 6;
    float var = (ws[half*2] + ws[half*2 + 1]) * (1.f / 64.f);
    const float* w = isq ? (half ? qnhw : qnw) : (half ? knhw : knw);
    float xn = w[d & 63] * x * rsqrtf(var + 1e-6f);

    __shared__ float xs[128];
    xs[d] = xn;
    __syncthreads();

    float outv;
    if (d < 64) {
        int i = d, jj = d & 31;
        float pos = (float)indexes[s];
        float f = powf(1000000.0f, -(float)jj * (1.0f / 32.0f));
        float a = pos * f;
        float c = cosf(a), sn = sinf(a);
        float prt = (i < 32) ? xs[d + 32] : xs[d - 32];
        outv = (i < 32) ? xn * c - prt * sn : xn * c + prt * sn;
    } else {
        int seg = (d < 96) ? 1 : 2;
        int base = (d < 96) ? 64 : 96;
        int i = d - base;
        int jj = i & 15;
        float pos = (float)indexes[seg * S + s];
        float f = powf(10000.0f, -(float)jj * (1.0f / 16.0f));
        float a = pos * f;
        float c = cosf(a), sn = sinf(a);
        float prt = (i < 16) ? xs[base + i + 16] : xs[base + i - 16];
        outv = (i < 16) ? xn * c - prt * sn : xn * c + prt * sn;
    }

    if (isq) Qo[((size_t)h * DH + d) * S + s] = outv;
    else     Ko[((size_t)(h - HQ) * DH + d) * S + s] = outv;
}

// ============================================================
// Causal flash attention v4: GEMM-GEMM, cp.async double-buffered K/V.
// Q/K arrive transposed [h][d][s]; Qs/Ks [d][q] at stride 64
// (16B aligned; every 8-lane 128B phase covers all 32 banks).
// Score: (tx,ty) 16x16 -> 4q x 4k.  PV: (vx,vy) 32x8 -> 8q x 4d.
// ============================================================
#define SP  65
#define QS_OFF  0
#define KS_OFF  (128*64)
#define VS_OFF  (KS_OFF + 2*128*64)
#define PS_OFF  (VS_OFF + 2*64*128)
#define AL_OFF  (PS_OFF + 64*SP)
#define LS_OFF  (AL_OFF + 64)
#define ATTN_SMEM_FLOATS (LS_OFF + 64)
#define ATTN_SMEM_BYTES  (ATTN_SMEM_FLOATS * 4)

__global__ __launch_bounds__(256, 1)
void attn4_kernel(const float* __restrict__ Q, const float* __restrict__ Kh,
                  const float* __restrict__ qkv, float* __restrict__ Out)
{
    extern __shared__ float sm[];
    float* Qs  = sm + QS_OFF;
    float* Ksb = sm + KS_OFF;
    float* Vsb = sm + VS_OFF;
    float* Ps  = sm + PS_OFF;
    float* als = sm + AL_OFF;
    float* ls  = sm + LS_OFF;

    const int qb = (int)(gridDim.x - 1 - blockIdx.x);   // longest first
    const int h  = blockIdx.y;
    const int kvh = h >> 1;
    const int q0 = qb * BQ;
    const int tid = threadIdx.x;
    const int tx = tid & 15, ty = tid >> 4;   // score mapping
    const int vx = tid & 31, vy = tid >> 5;   // PV mapping

    const float* Qbase = Q + (size_t)h * DH * S + q0;
    const float* Kbase = Kh + (size_t)kvh * DH * S;
    const float* Vbase = qkv + HQ*DH + HKV*DH + kvh*DH;   // V in qkv, stride QKVN

    const uint32_t qs_b = smem_u32(Qs);
    const uint32_t ks_b = smem_u32(Ksb);
    const uint32_t vs_b = smem_u32(Vsb);

    // per-thread load coords
    const int ldd = tid >> 4;            // 0..15 base row for K/Q (x8)
    const int lqq = (tid & 15) * 4;
    const int lr  = tid >> 5;            // 0..7 base row for V (x8)
    const int lc  = (tid & 31) * 4;

    // ---- group 0: Q tile + K/V tile 0 ----
    #pragma unroll
    for (int u = 0; u < 8; u++) {
        int dd = u * 16 + ldd;
        cp_async16(qs_b + (uint32_t)(dd*64 + lqq)*4, Qbase + (size_t)dd * S + lqq);
    }
    #pragma unroll
    for (int u = 0; u < 8; u++) {
        int dd = u * 16 + ldd;
        cp_async16(ks_b + (uint32_t)(dd*64 + lqq)*4, Kbase + (size_t)dd * S + lqq);
        int r = u * 8 + lr;
        cp_async16(vs_b + (uint32_t)(r*128 + lc)*4, Vbase + (size_t)r * QKVN + lc);
    }
    cp_commit();

    float o[8][4];
    #pragma unroll
    for (int i = 0; i < 8; i++)
        #pragma unroll
        for (int c = 0; c < 4; c++) o[i][c] = 0.f;
    float m[4], l[4];
    #pragma unroll
    for (int i = 0; i < 4; i++) { m[i] = -1e30f; l[i] = 0.f; }

    const int ntiles = qb + 1;
    for (int t = 0; t < ntiles; t++) {
        // ---- prefetch tile t+1 into buffer (t+1)&1 ----
        if (t + 1 < ntiles) {
            const int kt1 = (t + 1) * BK;
            const uint32_t kb = ks_b + (uint32_t)(((t+1)&1) * 128*64)*4;
            const uint32_t vb = vs_b + (uint32_t)(((t+1)&1) * 64*128)*4;
            #pragma unroll
            for (int u = 0; u < 8; u++) {
                int dd = u * 16 + ldd;
                cp_async16(kb + (uint32_t)(dd*64 + lqq)*4,
                           Kbase + (size_t)dd * S + kt1 + lqq);
                int r = u * 8 + lr;
                cp_async16(vb + (uint32_t)(r*128 + lc)*4,
                           Vbase + (size_t)(kt1 + r) * QKVN + lc);
            }
            cp_commit();
            cp_wait<1>();
        } else {
            cp_wait<0>();
        }
        __syncthreads();

        const float* Ks = Ksb + (t & 1) * 128*64;
        const float* Vs = Vsb + (t & 1) * 64*128;

        // ---- score GEMM: sc[4q][4k] ----
        float sc[4][4];
        #pragma unroll
        for (int i = 0; i < 4; i++)
            #pragma unroll
            for (int j = 0; j < 4; j++) sc[i][j] = 0.f;

        #pragma unroll 8
        for (int dd = 0; dd < 128; dd++) {
            float4 ra = *(const float4*)&Qs[dd*64 + ty*4];
            float4 rb = *(const float4*)&Ks[dd*64 + tx*4];
            float a[4] = {ra.x, ra.y, ra.z, ra.w};
            float b[4] = {rb.x, rb.y, rb.z, rb.w};
            #pragma unroll
            for (int i = 0; i < 4; i++)
                #pragma unroll
                for (int j = 0; j < 4; j++)
                    sc[i][j] += a[i] * b[j];
        }

        // ---- mask + scale (diagonal tile only) ----
        const bool needMask = (t == qb);
        #pragma unroll
        for (int i = 0; i < 4; i++) {
            int sq = q0 + ty*4 + i;
            #pragma unroll
            for (int j = 0; j < 4; j++) {
                int sk = t*BK + tx*4 + j;
                float v = sc[i][j] * SCALE;
                sc[i][j] = (!needMask || sk <= sq) ? v : -1e30f;
            }
        }

        // ---- online softmax (16-lane row groups via shfl) ----
        float alpha[4];
        #pragma unroll
        for (int i = 0; i < 4; i++) {
            float rm = fmaxf(fmaxf(sc[i][0], sc[i][1]), fmaxf(sc[i][2], sc[i][3]));
            rm = fmaxf(rm, __shfl_xor_sync(0xffffffffu, rm, 1));
            rm = fmaxf(rm, __shfl_xor_sync(0xffffffffu, rm, 2));
            rm = fmaxf(rm, __shfl_xor_sync(0xffffffffu, rm, 4));
            rm = fmaxf(rm, __shfl_xor_sync(0xffffffffu, rm, 8));
            float mn = fmaxf(m[i], rm);
            alpha[i] = __expf(m[i] - mn);
            m[i] = mn;
            float rs = 0.f;
            #pragma unroll
            for (int j = 0; j < 4; j++) {
                float p = __expf(sc[i][j] - mn);
                sc[i][j] = p;
                rs += p;
            }
            rs += __shfl_xor_sync(0xffffffffu, rs, 1);
            rs += __shfl_xor_sync(0xffffffffu, rs, 2);
            rs += __shfl_xor_sync(0xffffffffu, rs, 4);
            rs += __shfl_xor_sync(0xffffffffu, rs, 8);
            l[i] = l[i] * alpha[i] + rs;
        }

        // ---- stage P[k][q] (scalar, stride 65) + alpha ----
        #pragma unroll
        for (int j = 0; j < 4; j++)
            #pragma unroll
            for (int i = 0; i < 4; i++)
                Ps[(tx*4 + j)*SP + ty*4 + i] = sc[i][j];
        if (tx == 0) {
            #pragma unroll
            for (int i = 0; i < 4; i++) als[ty*4 + i] = alpha[i];
        }
        __syncthreads();

        // ---- PV: rescale + accumulate ----
        #pragma unroll
        for (int i = 0; i < 8; i++) {
            float a = als[vy*8 + i];
            #pragma unroll
            for (int c = 0; c < 4; c++) o[i][c] *= a;
        }
        #pragma unroll 4
        for (int kk = 0; kk < BK; kk++) {
            float ra[8];
            #pragma unroll
            for (int i = 0; i < 8; i++) ra[i] = Ps[kk*SP + vy*8 + i];  // broadcast
            float4 rb = *(const float4*)&Vs[kk*128 + vx*4];
            #pragma unroll
            for (int i = 0; i < 8; i++) {
                o[i][0] += ra[i] * rb.x;
                o[i][1] += ra[i] * rb.y;
                o[i][2] += ra[i] * rb.z;
                o[i][3] += ra[i] * rb.w;
            }
        }
        __syncthreads();   // all done with Ks/Vs/Ps before next prefetch overwrites
    }

    // ---- epilogue ----
    if (tx == 0) {
        #pragma unroll
        for (int i = 0; i < 4; i++) ls[ty*4 + i] = l[i];
    }
    __syncthreads();
    #pragma unroll
    for (int i = 0; i < 8; i++) {
        float inv = 1.f / ls[vy*8 + i];
        float4 ov;
        ov.x = o[i][0]*inv; ov.y = o[i][1]*inv;
        ov.z = o[i][2]*inv; ov.w = o[i][3]*inv;
        *(float4*)(Out + (size_t)(q0 + vy*8 + i) * (HQ*DH) + h*DH + vx*4) = ov;
    }
}

// ============================================================
extern "C" void kernel_launch(void* const* d_in, const int* in_sizes, int n_in,
                              void* d_out, int out_size)
{
    const float* hidden  = (const float*)d_in[0];
    const int*   indexes = (const int*)  d_in[1];
    // d_in[2] = attention_mask (causal by construction; applied analytically)
    const float* qkv_w   = (const float*)d_in[3];
    const float* qkv_b   = (const float*)d_in[4];
    const float* o_w     = (const float*)d_in[5];
    const float* o_b     = (const float*)d_in[6];
    const float* qnw     = (const float*)d_in[7];
    const float* knw     = (const float*)d_in[8];
    const float* qnhw    = (const float*)d_in[9];
    const float* knhw    = (const float*)d_in[10];
    float* out = (float*)d_out;

    float *p_qkv, *p_q, *p_k, *p_attn;
    cudaGetSymbolAddress((void**)&p_qkv,  g_qkv);
    cudaGetSymbolAddress((void**)&p_q,    g_q);
    cudaGetSymbolAddress((void**)&p_k,    g_k);
    cudaGetSymbolAddress((void**)&p_attn, g_attn);

    cudaFuncSetAttribute(attn4_kernel,
                         cudaFuncAttributeMaxDynamicSharedMemorySize, ATTN_SMEM_BYTES);

    // 1) QKV projection
    sgemm_abt<<<dim3(QKVN/128, S/128), 256>>>(hidden, qkv_w, qkv_b, p_qkv, S, QKVN, HIDN);
    // 2) RMSNorm halves + triple RoPE -> Q [H,D,S], K [KV,D,S] (transposed)
    normrope_kernel<<<dim3(S, HQ + HKV), 128>>>(p_qkv, indexes, qnw, knw, qnhw, knhw, p_q, p_k);
    // 3) Causal GQA flash attention -> attn [S, H*D]
    attn4_kernel<<<dim3(S/BQ, HQ), 256, ATTN_SMEM_BYTES>>>(p_q, p_k, p_qkv, p_attn);
    // 4) Output projection
    sgemm_abt<<<dim3(HIDN/128, S/128), 256>>>(p_attn, o_w, o_b, out, S, HIDN, HIDN);
}